// round 1
// baseline (speedup 1.0000x reference)
#include <cuda_runtime.h>
#include <math.h>

#define HD 128
#define NN 256
#define NB 16

// Scratch (allocation-free rule: __device__ globals)
__device__ float g_g[NN][HD];    // scan output (GEMM input)
__device__ float g_h[NN][HD];    // layer output
__device__ float g_A0[NN][HD];   // h3 @ W1a + b1   (batch 0)
__device__ float g_B0[NN][HD];   // h3 @ W1b        (batch 0)
__device__ float g_pb[NB];       // constant edge prob per batch (b>=1)

// ---------------------------------------------------------------------------
// K1: embeddings for all batches; full chain for b>=1 (node-constant);
//     batch-0 layer-1 (rank-1 structure) fused with the scan for layer 2.
// grid 16 x 128 threads
// ---------------------------------------------------------------------------
__global__ void k_prep(const float* __restrict__ z, const float* __restrict__ We,
                       const float* __restrict__ be, const float* __restrict__ Wg,
                       const float* __restrict__ bg, const float* __restrict__ W1a,
                       const float* __restrict__ W1b, const float* __restrict__ b1,
                       const float* __restrict__ W2, const float* __restrict__ b2) {
    int b = blockIdx.x;
    int d = threadIdx.x;
    __shared__ float zs[64];
    __shared__ float v[HD];
    if (d < 64) zs[d] = z[b * 64 + d];
    __syncthreads();
    float emb = be[d];
#pragma unroll 8
    for (int k = 0; k < 64; k++) emb = fmaf(zs[k], We[k * HD + d], emb);
    v[d] = emb;
    __syncthreads();

    if (b == 0) {
        // u = emb0 @ Wg[0]
        float u = 0.f;
#pragma unroll 8
        for (int k = 0; k < HD; k++) u = fmaf(v[k], Wg[k * HD + d], u);
        float bg0 = bg[d];
        // h1[j] = relu(sc[j]*u + bg0), sc[j] = dinv[j]*Dex[j] + dinv[j]^2
        // fused exclusive scan for layer-2 input:
        // g[j] = dinv[j]*c + dinv[j]^2*h1[j],  c = sum_{i<j} dinv[i]*h1[i]
        float c = 0.f, Dex = 0.f;
        for (int j = 0; j < NN; j++) {
            float dinv = rsqrtf((float)(j + 1));
            float sc = fmaf(dinv, Dex, dinv * dinv);
            float h1 = fmaxf(fmaf(sc, u, bg0), 0.f);
            g_g[j][d] = fmaf(dinv, c, dinv * dinv * h1);
            c = fmaf(dinv, h1, c);
            Dex += dinv;
        }
    } else {
        // node-constant chain: 3 GCN layers (no aggregation change for b>=1)
        for (int l = 0; l < 3; l++) {
            const float* W = Wg + l * HD * HD;
            float a = bg[l * HD + d];
#pragma unroll 8
            for (int k = 0; k < HD; k++) a = fmaf(v[k], W[k * HD + d], a);
            a = fmaxf(a, 0.f);
            __syncthreads();
            v[d] = a;
            __syncthreads();
        }
        // single scalar logit: relu(v@W1a + b1 + v@W1b) . W2 + b2
        float a = b1[d], bb = 0.f;
#pragma unroll 4
        for (int k = 0; k < HD; k++) {
            float vk = v[k];
            a  = fmaf(vk, W1a[k * HD + d], a);
            bb = fmaf(vk, W1b[k * HD + d], bb);
        }
        float t = fmaxf(a + bb, 0.f) * W2[d];
        for (int off = 16; off > 0; off >>= 1)
            t += __shfl_down_sync(0xffffffffu, t, off);
        __shared__ float ws[4];
        if ((d & 31) == 0) ws[d >> 5] = t;
        __syncthreads();
        if (d == 0) {
            float s = ws[0] + ws[1] + ws[2] + ws[3] + b2[0];
            g_pb[b] = 1.f / (1.f + expf(-s));
        }
    }
}

// ---------------------------------------------------------------------------
// K2: h = relu(g_g @ W + bias) for batch 0 (layer 2)
// grid 32 x 256 threads, 8 rows/block, one warp per row, float4 over dims
// ---------------------------------------------------------------------------
__global__ void k_mm(const float* __restrict__ W, const float* __restrict__ bias) {
    int warp = threadIdx.x >> 5, lane = threadIdx.x & 31;
    int base = blockIdx.x * 8;
    __shared__ float gs[8][HD];
    for (int idx = threadIdx.x; idx < 8 * HD; idx += 256)
        gs[idx >> 7][idx & 127] = g_g[base + (idx >> 7)][idx & 127];
    __syncthreads();
    const float4* W4 = (const float4*)W;
    float4 acc = ((const float4*)bias)[lane];
#pragma unroll 4
    for (int k = 0; k < HD; k++) {
        float g = gs[warp][k];
        float4 w = W4[k * 32 + lane];
        acc.x = fmaf(g, w.x, acc.x);
        acc.y = fmaf(g, w.y, acc.y);
        acc.z = fmaf(g, w.z, acc.z);
        acc.w = fmaf(g, w.w, acc.w);
    }
    acc.x = fmaxf(acc.x, 0.f); acc.y = fmaxf(acc.y, 0.f);
    acc.z = fmaxf(acc.z, 0.f); acc.w = fmaxf(acc.w, 0.f);
    ((float4*)g_h[base + warp])[lane] = acc;
}

// ---------------------------------------------------------------------------
// K3: exclusive dinv-weighted scan over nodes: g_h -> g_g
// 1 block x 128 threads (one per dim)
// ---------------------------------------------------------------------------
__global__ void k_scan() {
    int d = threadIdx.x;
    float c = 0.f;
#pragma unroll 8
    for (int j = 0; j < NN; j++) {
        float h = g_h[j][d];
        float dinv = rsqrtf((float)(j + 1));
        g_g[j][d] = fmaf(dinv, c, dinv * dinv * h);
        c = fmaf(dinv, h, c);
    }
}

// ---------------------------------------------------------------------------
// K4: layer 3 GEMM+ReLU fused with A0 = h3@W1a + b1, B0 = h3@W1b
// grid 32 x 256 threads
// ---------------------------------------------------------------------------
__global__ void k_mm3(const float* __restrict__ Wg2, const float* __restrict__ bg2,
                      const float* __restrict__ W1a, const float* __restrict__ W1b,
                      const float* __restrict__ b1) {
    int warp = threadIdx.x >> 5, lane = threadIdx.x & 31;
    int base = blockIdx.x * 8;
    __shared__ float gs[8][HD];
    __shared__ float hs[8][HD];
    for (int idx = threadIdx.x; idx < 8 * HD; idx += 256)
        gs[idx >> 7][idx & 127] = g_g[base + (idx >> 7)][idx & 127];
    __syncthreads();
    const float4* W4 = (const float4*)Wg2;
    float4 acc = ((const float4*)bg2)[lane];
#pragma unroll 4
    for (int k = 0; k < HD; k++) {
        float g = gs[warp][k];
        float4 w = W4[k * 32 + lane];
        acc.x = fmaf(g, w.x, acc.x);
        acc.y = fmaf(g, w.y, acc.y);
        acc.z = fmaf(g, w.z, acc.z);
        acc.w = fmaf(g, w.w, acc.w);
    }
    acc.x = fmaxf(acc.x, 0.f); acc.y = fmaxf(acc.y, 0.f);
    acc.z = fmaxf(acc.z, 0.f); acc.w = fmaxf(acc.w, 0.f);
    ((float4*)hs[warp])[lane] = acc;
    __syncthreads();

    const float4* Wa4 = (const float4*)W1a;
    const float4* Wb4 = (const float4*)W1b;
    float4 aA = ((const float4*)b1)[lane];
    float4 aB = make_float4(0.f, 0.f, 0.f, 0.f);
#pragma unroll 2
    for (int k = 0; k < HD; k++) {
        float h = hs[warp][k];
        float4 wa = Wa4[k * 32 + lane];
        float4 wb = Wb4[k * 32 + lane];
        aA.x = fmaf(h, wa.x, aA.x); aA.y = fmaf(h, wa.y, aA.y);
        aA.z = fmaf(h, wa.z, aA.z); aA.w = fmaf(h, wa.w, aA.w);
        aB.x = fmaf(h, wb.x, aB.x); aB.y = fmaf(h, wb.y, aB.y);
        aB.z = fmaf(h, wb.z, aB.z); aB.w = fmaf(h, wb.w, aB.w);
    }
    ((float4*)g_A0[base + warp])[lane] = aA;
    ((float4*)g_B0[base + warp])[lane] = aB;
}

// ---------------------------------------------------------------------------
// K5: output. b>=1 : constant fill (diag 0). b==0 : pairwise edge predictor,
// only i<j computed (upper-incl-diag blocks), mirror written via smem transpose.
// grid (8,8,16) x 256 threads
// ---------------------------------------------------------------------------
__global__ void k_out(const float* __restrict__ W2, const float* __restrict__ b2,
                      float* __restrict__ out) {
    int b = blockIdx.z;
    int tid = threadIdx.x;
    if (b > 0) {
        float p = g_pb[b];
        int r = tid >> 3, c4 = tid & 7;
        int i = blockIdx.y * 32 + r;
        int j0 = blockIdx.x * 32 + c4 * 4;
        float4 v;
        v.x = (i == j0 + 0) ? 0.f : p;
        v.y = (i == j0 + 1) ? 0.f : p;
        v.z = (i == j0 + 2) ? 0.f : p;
        v.w = (i == j0 + 3) ? 0.f : p;
        *((float4*)(out + (((size_t)b * NN + i) * NN + j0))) = v;
        return;
    }
    int by = blockIdx.y, bx = blockIdx.x;
    if (by > bx) return;  // lower blocks covered by mirror writes
    __shared__ float a_sh[32 * 129];
    __shared__ float b_sh[32 * 129];
    __shared__ float w2s[HD];
    __shared__ float b2s;
    __shared__ float tile[32][33];
    for (int idx = tid; idx < 32 * HD; idx += 256) {
        int r = idx >> 7, d = idx & 127;
        a_sh[r * 129 + d] = g_A0[by * 32 + r][d];
        b_sh[r * 129 + d] = g_B0[bx * 32 + r][d];
    }
    if (tid < HD) w2s[tid] = W2[tid];
    if (tid == 0) b2s = b2[0];
    __syncthreads();

    int jl = tid & 31, il0 = tid >> 5;
#pragma unroll
    for (int q = 0; q < 4; q++) {
        int il = il0 + 8 * q;
        int gi = by * 32 + il, gj = bx * 32 + jl;
        float val = 0.f;
        if (gi < gj) {
            float acc = 0.f;
#pragma unroll 8
            for (int d = 0; d < HD; d++) {
                float h = fmaxf(a_sh[il * 129 + d] + b_sh[jl * 129 + d], 0.f);
                acc = fmaf(h, w2s[d], acc);
            }
            val = 1.f / (1.f + expf(-(acc + b2s)));
        }
        tile[il][jl] = val;
    }
    __syncthreads();

    // upper block write (for by==bx, fill from symmetric entry / diag 0)
    for (int idx = tid; idx < 1024; idx += 256) {
        int r = idx >> 5, c = idx & 31;
        float v;
        if (by == bx)
            v = (r < c) ? tile[r][c] : ((r > c) ? tile[c][r] : 0.f);
        else
            v = tile[r][c];
        out[((size_t)(by * 32 + r)) * NN + bx * 32 + c] = v;
    }
    // mirror block write (transposed, conflict-free via 33-stride)
    if (by < bx) {
        for (int idx = tid; idx < 1024; idx += 256) {
            int r = idx >> 5, c = idx & 31;
            out[((size_t)(bx * 32 + r)) * NN + by * 32 + c] = tile[c][r];
        }
    }
}

// ---------------------------------------------------------------------------
extern "C" void kernel_launch(void* const* d_in, const int* in_sizes, int n_in,
                              void* d_out, int out_size) {
    const float* z   = (const float*)d_in[0];
    const float* We  = (const float*)d_in[1];
    const float* be  = (const float*)d_in[2];
    const float* Wg  = (const float*)d_in[3];
    const float* bg  = (const float*)d_in[4];
    const float* W1a = (const float*)d_in[5];
    const float* W1b = (const float*)d_in[6];
    const float* b1  = (const float*)d_in[7];
    const float* W2  = (const float*)d_in[8];
    const float* b2  = (const float*)d_in[9];
    float* out = (float*)d_out;

    k_prep<<<16, 128>>>(z, We, be, Wg, bg, W1a, W1b, b1, W2, b2);
    k_mm<<<32, 256>>>(Wg + 1 * HD * HD, bg + 1 * HD);   // layer 2
    k_scan<<<1, 128>>>();
    k_mm3<<<32, 256>>>(Wg + 2 * HD * HD, bg + 2 * HD, W1a, W1b, b1);
    k_out<<<dim3(8, 8, 16), 256>>>(W2, b2, out);
}

// round 2
// speedup vs baseline: 2.9556x; 2.9556x over previous
#include <cuda_runtime.h>
#include <math.h>

#define HD 128
#define NN 256
#define NB 16

// Scratch (allocation-free rule: __device__ globals)
__device__ float g_g[NN][HD];    // scan output (layer-2 GEMM input)
__device__ float g_h[NN][HD];    // layer-2 output (relu)
__device__ float g_P[32][HD];    // per-block partial sums of dinv*h (for scan)
__device__ float g_A0[NN][HD];   // h3 @ W1a + b1   (batch 0)
__device__ float g_B0[NN][HD];   // h3 @ W1b        (batch 0)
__device__ float g_pb[NB];       // constant edge prob per batch (b>=1)

// ---------------------------------------------------------------------------
// K1: embeddings for all batches; full chain for b>=1 (node-constant);
//     batch-0 layer-1 (rank-1) fused with scan for layer-2 input.
// grid 16 x 256 threads. k-dim split across two 128-thread halves.
// ---------------------------------------------------------------------------
__global__ void k_prep(const float* __restrict__ z, const float* __restrict__ We,
                       const float* __restrict__ be, const float* __restrict__ Wg,
                       const float* __restrict__ bg, const float* __restrict__ W1a,
                       const float* __restrict__ W1b, const float* __restrict__ b1,
                       const float* __restrict__ W2, const float* __restrict__ b2) {
    int b = blockIdx.x;
    int tid = threadIdx.x;
    int d = tid & 127;
    int hf = tid >> 7;           // 0 or 1: which k-half this thread covers
    __shared__ float zs[64];
    __shared__ float v[HD];
    __shared__ float red[2][HD];
    __shared__ float ws[8];
    if (tid < 64) zs[tid] = z[b * 64 + tid];
    __syncthreads();
    // embedding: emb[d] = sum_k z[k] * We[k][d] + be[d]  (k split 32/32)
    {
        int k0 = hf * 32;
        float a0 = 0.f, a1 = 0.f;
#pragma unroll
        for (int k = 0; k < 32; k += 2) {
            a0 = fmaf(zs[k0 + k],     We[(k0 + k) * HD + d],     a0);
            a1 = fmaf(zs[k0 + k + 1], We[(k0 + k + 1) * HD + d], a1);
        }
        red[hf][d] = a0 + a1;
    }
    __syncthreads();
    if (hf == 0) v[d] = red[0][d] + red[1][d] + be[d];
    __syncthreads();

    if (b == 0) {
        // u = emb0 @ Wg[0] (k split 64/64)
        int k0 = hf * 64;
        float a0 = 0.f, a1 = 0.f;
#pragma unroll
        for (int k = 0; k < 64; k += 2) {
            a0 = fmaf(v[k0 + k],     Wg[(k0 + k) * HD + d],     a0);
            a1 = fmaf(v[k0 + k + 1], Wg[(k0 + k + 1) * HD + d], a1);
        }
        red[hf][d] = a0 + a1;
        __syncthreads();
        if (hf == 0) {
            float u = red[0][d] + red[1][d];
            float bg0 = bg[d];
            // h1[j] = relu(sc[j]*u + bg0); fused exclusive scan for layer-2 input
            float c = 0.f, Dex = 0.f;
            for (int j = 0; j < NN; j++) {
                float dinv = rsqrtf((float)(j + 1));
                float sc = fmaf(dinv, Dex, dinv * dinv);
                float h1 = fmaxf(fmaf(sc, u, bg0), 0.f);
                g_g[j][d] = fmaf(dinv, c, dinv * dinv * h1);
                c = fmaf(dinv, h1, c);
                Dex += dinv;
            }
        }
    } else {
        // node-constant chain: 3 GCN layers (aggregation is identity for b>=1)
        for (int l = 0; l < 3; l++) {
            const float* W = Wg + l * HD * HD;
            int k0 = hf * 64;
            float a0 = 0.f, a1 = 0.f;
#pragma unroll
            for (int k = 0; k < 64; k += 2) {
                a0 = fmaf(v[k0 + k],     W[(k0 + k) * HD + d],     a0);
                a1 = fmaf(v[k0 + k + 1], W[(k0 + k + 1) * HD + d], a1);
            }
            red[hf][d] = a0 + a1;
            __syncthreads();
            if (hf == 0) v[d] = fmaxf(red[0][d] + red[1][d] + bg[l * HD + d], 0.f);
            __syncthreads();
        }
        // single scalar logit per batch
        {
            int k0 = hf * 64;
            float a0 = 0.f, b0 = 0.f;
#pragma unroll
            for (int k = 0; k < 64; k++) {
                float vk = v[k0 + k];
                a0 = fmaf(vk, W1a[(k0 + k) * HD + d], a0);
                b0 = fmaf(vk, W1b[(k0 + k) * HD + d], b0);
            }
            red[hf][d] = a0 + b0;
        }
        __syncthreads();
        float t = 0.f;
        if (hf == 0) t = fmaxf(red[0][d] + red[1][d] + b1[d], 0.f) * W2[d];
        for (int off = 16; off > 0; off >>= 1)
            t += __shfl_down_sync(0xffffffffu, t, off);
        if ((tid & 31) == 0) ws[tid >> 5] = t;
        __syncthreads();
        if (tid == 0) {
            float s = ws[0] + ws[1] + ws[2] + ws[3] + b2[0];  // ws[4..7] are 0
            g_pb[b] = 1.f / (1.f + expf(-s));
        }
    }
}

// ---------------------------------------------------------------------------
// K2: layer-2 GEMM for batch 0: g_h = relu(g_g @ W + bias), plus per-block
// partial sums g_P[bk][d] = sum_{j in block} dinv_j * h_j[d].
// grid 32 x 256, 8 rows/block, weights staged in smem (two 32KB halves).
// ---------------------------------------------------------------------------
__global__ void k_mm(const float* __restrict__ W, const float* __restrict__ bias) {
    __shared__ float Ws[64 * HD];     // 32 KB: one k-half of W
    __shared__ float gs[8][HD];
    __shared__ float hs[8][HD];
    int tid = threadIdx.x, warp = tid >> 5, lane = tid & 31;
    int base = blockIdx.x * 8;
    // stage input rows
    for (int i = tid; i < 8 * HD / 4; i += 256)
        ((float4*)gs)[i] = ((const float4*)&g_g[base][0])[i];

    const float4* W4 = (const float4*)W;
    float4 acc = ((const float4*)bias)[lane];
#pragma unroll
    for (int half = 0; half < 2; half++) {
        __syncthreads();
        for (int i = tid; i < 2048; i += 256)
            ((float4*)Ws)[i] = W4[half * 2048 + i];
        __syncthreads();
        const float4* Ws4 = (const float4*)Ws;
#pragma unroll 8
        for (int k = 0; k < 64; k++) {
            float g = gs[warp][half * 64 + k];
            float4 w = Ws4[k * 32 + lane];
            acc.x = fmaf(g, w.x, acc.x);
            acc.y = fmaf(g, w.y, acc.y);
            acc.z = fmaf(g, w.z, acc.z);
            acc.w = fmaf(g, w.w, acc.w);
        }
    }
    acc.x = fmaxf(acc.x, 0.f); acc.y = fmaxf(acc.y, 0.f);
    acc.z = fmaxf(acc.z, 0.f); acc.w = fmaxf(acc.w, 0.f);
    ((float4*)&g_h[base + warp][0])[lane] = acc;
    // dinv-scaled copy for partial sum
    float dj = rsqrtf((float)(base + warp + 1));
    float4 sc = make_float4(acc.x * dj, acc.y * dj, acc.z * dj, acc.w * dj);
    ((float4*)&hs[warp][0])[lane] = sc;
    __syncthreads();
    if (tid < HD) {
        float s = 0.f;
#pragma unroll
        for (int w = 0; w < 8; w++) s += hs[w][tid];
        g_P[blockIdx.x][tid] = s;
    }
}

// ---------------------------------------------------------------------------
// K3: inline scan (from g_h + g_P) -> layer-3 GEMM+ReLU -> A0/B0 GEMMs.
// grid 32 x 256, weights staged in smem.
// ---------------------------------------------------------------------------
__global__ void k_mm3(const float* __restrict__ Wg2, const float* __restrict__ bg2,
                      const float* __restrict__ W1a, const float* __restrict__ W1b,
                      const float* __restrict__ b1) {
    __shared__ float Ws[64 * HD];     // 32 KB
    __shared__ float gs[8][HD];
    __shared__ float hs[8][HD];
    int tid = threadIdx.x, warp = tid >> 5, lane = tid & 31;
    int bk = blockIdx.x, base = bk * 8;

    // scan prologue: reconstruct exclusive prefix from partials, build gs
    if (tid < HD) {
        int d = tid;
        float c = 0.f;
        for (int p = 0; p < bk; p++) c += g_P[p][d];
#pragma unroll
        for (int j = 0; j < 8; j++) {
            int n = base + j;
            float dinv = rsqrtf((float)(n + 1));
            float h = g_h[n][d];
            gs[j][d] = fmaf(dinv, c, dinv * dinv * h);
            c = fmaf(dinv, h, c);
        }
    }

    const float4* Wg4 = (const float4*)Wg2;
    float4 acc = ((const float4*)bg2)[lane];
#pragma unroll
    for (int half = 0; half < 2; half++) {
        __syncthreads();
        for (int i = tid; i < 2048; i += 256)
            ((float4*)Ws)[i] = Wg4[half * 2048 + i];
        __syncthreads();
        const float4* Ws4 = (const float4*)Ws;
#pragma unroll 8
        for (int k = 0; k < 64; k++) {
            float g = gs[warp][half * 64 + k];
            float4 w = Ws4[k * 32 + lane];
            acc.x = fmaf(g, w.x, acc.x);
            acc.y = fmaf(g, w.y, acc.y);
            acc.z = fmaf(g, w.z, acc.z);
            acc.w = fmaf(g, w.w, acc.w);
        }
    }
    acc.x = fmaxf(acc.x, 0.f); acc.y = fmaxf(acc.y, 0.f);
    acc.z = fmaxf(acc.z, 0.f); acc.w = fmaxf(acc.w, 0.f);
    ((float4*)&hs[warp][0])[lane] = acc;   // h3 rows in smem

    // A0 = h3 @ W1a + b1
    const float4* Wa4 = (const float4*)W1a;
    float4 aA = ((const float4*)b1)[lane];
#pragma unroll
    for (int half = 0; half < 2; half++) {
        __syncthreads();
        for (int i = tid; i < 2048; i += 256)
            ((float4*)Ws)[i] = Wa4[half * 2048 + i];
        __syncthreads();
        const float4* Ws4 = (const float4*)Ws;
#pragma unroll 8
        for (int k = 0; k < 64; k++) {
            float h = hs[warp][half * 64 + k];
            float4 w = Ws4[k * 32 + lane];
            aA.x = fmaf(h, w.x, aA.x);
            aA.y = fmaf(h, w.y, aA.y);
            aA.z = fmaf(h, w.z, aA.z);
            aA.w = fmaf(h, w.w, aA.w);
        }
    }
    ((float4*)&g_A0[base + warp][0])[lane] = aA;

    // B0 = h3 @ W1b
    const float4* Wb4 = (const float4*)W1b;
    float4 aB = make_float4(0.f, 0.f, 0.f, 0.f);
#pragma unroll
    for (int half = 0; half < 2; half++) {
        __syncthreads();
        for (int i = tid; i < 2048; i += 256)
            ((float4*)Ws)[i] = Wb4[half * 2048 + i];
        __syncthreads();
        const float4* Ws4 = (const float4*)Ws;
#pragma unroll 8
        for (int k = 0; k < 64; k++) {
            float h = hs[warp][half * 64 + k];
            float4 w = Ws4[k * 32 + lane];
            aB.x = fmaf(h, w.x, aB.x);
            aB.y = fmaf(h, w.y, aB.y);
            aB.z = fmaf(h, w.z, aB.z);
            aB.w = fmaf(h, w.w, aB.w);
        }
    }
    ((float4*)&g_B0[base + warp][0])[lane] = aB;
}

// ---------------------------------------------------------------------------
// K4: batch-0 pairwise edge predictor. 16x16 tiles over the upper triangle
// (incl. diagonal), mirror written transposed. 136 blocks x 256 threads.
// ---------------------------------------------------------------------------
__global__ void k_pair(const float* __restrict__ W2, const float* __restrict__ b2,
                       float* __restrict__ out) {
    // map linear block id -> (ti, tj), ti <= tj, 16 tiles per side
    int ti = 0, rem = blockIdx.x;
    while (rem >= 16 - ti) { rem -= 16 - ti; ti++; }
    int tj = ti + rem;

    __shared__ float a_sh[16][132];
    __shared__ float b_sh[16][132];
    __shared__ float w2s[HD];
    __shared__ float b2s;
    __shared__ float tile[16][17];
    int tid = threadIdx.x;
    // stage A rows (ti tile) and B rows (tj tile): 512 float4 each
    for (int i = tid; i < 512; i += 256) {
        int r = i >> 5, d4 = i & 31;
        ((float4*)&a_sh[r][0])[d4] = ((const float4*)&g_A0[ti * 16 + r][0])[d4];
        ((float4*)&b_sh[r][0])[d4] = ((const float4*)&g_B0[tj * 16 + r][0])[d4];
    }
    if (tid < HD) w2s[tid] = W2[tid];
    if (tid == 0) b2s = b2[0];
    __syncthreads();

    int il = tid >> 4, jl = tid & 15;
    float acc = 0.f;
    const float4* a4 = (const float4*)&a_sh[il][0];
    const float4* b4 = (const float4*)&b_sh[jl][0];
    const float4* w4 = (const float4*)w2s;
#pragma unroll
    for (int q = 0; q < 32; q++) {
        float4 a = a4[q], b = b4[q], w = w4[q];
        acc = fmaf(fmaxf(a.x + b.x, 0.f), w.x, acc);
        acc = fmaf(fmaxf(a.y + b.y, 0.f), w.y, acc);
        acc = fmaf(fmaxf(a.z + b.z, 0.f), w.z, acc);
        acc = fmaf(fmaxf(a.w + b.w, 0.f), w.w, acc);
    }
    tile[il][jl] = 1.f / (1.f + expf(-(acc + b2s)));
    __syncthreads();

    int r = tid >> 4, c = tid & 15;
    if (ti == tj) {
        float v = (r < c) ? tile[r][c] : ((r > c) ? tile[c][r] : 0.f);
        out[((size_t)(ti * 16 + r)) * NN + ti * 16 + c] = v;
    } else {
        out[((size_t)(ti * 16 + r)) * NN + tj * 16 + c] = tile[r][c];
        out[((size_t)(tj * 16 + r)) * NN + ti * 16 + c] = tile[c][r];
    }
}

// ---------------------------------------------------------------------------
// K5: constant fill for b >= 1 (diag 0). grid (8,8,15) x 256 threads.
// ---------------------------------------------------------------------------
__global__ void k_fill(float* __restrict__ out) {
    int b = blockIdx.z + 1;
    float p = g_pb[b];
    int tid = threadIdx.x;
    int r = tid >> 3, c4 = tid & 7;
    int i = blockIdx.y * 32 + r;
    int j0 = blockIdx.x * 32 + c4 * 4;
    float4 v;
    v.x = (i == j0 + 0) ? 0.f : p;
    v.y = (i == j0 + 1) ? 0.f : p;
    v.z = (i == j0 + 2) ? 0.f : p;
    v.w = (i == j0 + 3) ? 0.f : p;
    *((float4*)(out + (((size_t)b * NN + i) * NN + j0))) = v;
}

// ---------------------------------------------------------------------------
extern "C" void kernel_launch(void* const* d_in, const int* in_sizes, int n_in,
                              void* d_out, int out_size) {
    const float* z   = (const float*)d_in[0];
    const float* We  = (const float*)d_in[1];
    const float* be  = (const float*)d_in[2];
    const float* Wg  = (const float*)d_in[3];
    const float* bg  = (const float*)d_in[4];
    const float* W1a = (const float*)d_in[5];
    const float* W1b = (const float*)d_in[6];
    const float* b1  = (const float*)d_in[7];
    const float* W2  = (const float*)d_in[8];
    const float* b2  = (const float*)d_in[9];
    float* out = (float*)d_out;

    k_prep<<<16, 256>>>(z, We, be, Wg, bg, W1a, W1b, b1, W2, b2);
    k_mm<<<32, 256>>>(Wg + 1 * HD * HD, bg + 1 * HD);     // layer 2
    k_mm3<<<32, 256>>>(Wg + 2 * HD * HD, bg + 2 * HD, W1a, W1b, b1);
    k_pair<<<136, 256>>>(W2, b2, out);
    k_fill<<<dim3(8, 8, 15), 256>>>(out);
}

// round 3
// speedup vs baseline: 3.3152x; 1.1217x over previous
#include <cuda_runtime.h>
#include <math.h>

#define HD 128
#define NN 256
#define NB 16

// Scratch (allocation-free rule: __device__ globals)
__device__ float g_h[NN][HD];    // layer-2 output (relu)
__device__ float g_P[32][HD];    // per-block partial sums of dinv*h (for scan)
__device__ float g_A0[NN][HD];   // h3 @ W1a + b1   (batch 0)
__device__ float g_B0[NN][HD];   // h3 @ W1b        (batch 0)
__device__ float g_pb[NB];       // constant edge prob per batch (b>=1)

// ---------------------------------------------------------------------------
// K1: blocks 0..31  : batch-0 fused (closed-form layer-1 + scan, redundant per
//                     block) -> layer-2 GEMM (double-buffered 16KB quarters)
//                     -> g_h rows + per-block dinv partial sums g_P.
//     blocks 32..46 : node-constant chains for b = 1..15 -> g_pb.
// grid 47 x 256
// ---------------------------------------------------------------------------
__global__ void k1(const float* __restrict__ z, const float* __restrict__ We,
                   const float* __restrict__ be, const float* __restrict__ Wg,
                   const float* __restrict__ bg, const float* __restrict__ W1a,
                   const float* __restrict__ W1b, const float* __restrict__ b1,
                   const float* __restrict__ W2, const float* __restrict__ b2) {
    __shared__ __align__(16) float buf[2][4096];   // 2 x 16KB weight quarters
    __shared__ __align__(16) float gs[8][HD];
    __shared__ __align__(16) float hs[8][HD];
    __shared__ float zs[64];
    __shared__ float red[2][HD];
    __shared__ float vv[HD];
    __shared__ float wsum[8];

    int tid = threadIdx.x;
    int bk = blockIdx.x;
    int d = tid & 127, hf = tid >> 7;

    if (bk < 32) {
        int warp = tid >> 5, lane = tid & 31;
        const float4* W14 = (const float4*)(Wg + HD * HD);  // layer-2 weight
        // prefetch quarter 0 of layer-2 weight (hidden behind prologue)
        float4 p0 = W14[tid], p1 = W14[256 + tid], p2 = W14[512 + tid], p3 = W14[768 + tid];

        if (tid < 64) zs[tid] = z[tid];
        __syncthreads();
        {   // embedding emb[d] (batch 0), k split 32/32
            int k0 = hf * 32;
            float a0 = 0.f, a1 = 0.f;
#pragma unroll
            for (int k = 0; k < 32; k += 2) {
                a0 = fmaf(zs[k0 + k],     We[(k0 + k) * HD + d],     a0);
                a1 = fmaf(zs[k0 + k + 1], We[(k0 + k + 1) * HD + d], a1);
            }
            red[hf][d] = a0 + a1;
        }
        __syncthreads();
        if (hf == 0) vv[d] = red[0][d] + red[1][d] + be[d];
        __syncthreads();
        {   // u = emb @ Wg[0], k split 64/64
            int k0 = hf * 64;
            float a0 = 0.f, a1 = 0.f;
#pragma unroll
            for (int k = 0; k < 64; k += 2) {
                a0 = fmaf(vv[k0 + k],     Wg[(k0 + k) * HD + d],     a0);
                a1 = fmaf(vv[k0 + k + 1], Wg[(k0 + k + 1) * HD + d], a1);
            }
            red[hf][d] = a0 + a1;
        }
        __syncthreads();
        if (hf == 0) {
            // closed-form layer-1 + exclusive dinv-scan, up to this block's rows
            float u = red[0][d] + red[1][d];
            float bg0 = bg[d];
            float c = 0.f, Dex = 0.f;
            int base = bk * 8;
            for (int j = 0; j < base + 8; j++) {
                float dinv = rsqrtf((float)(j + 1));
                float sc = fmaf(dinv, Dex, dinv * dinv);
                float h1 = fmaxf(fmaf(sc, u, bg0), 0.f);
                if (j >= base) gs[j - base][d] = fmaf(dinv, c, dinv * dinv * h1);
                c = fmaf(dinv, h1, c);
                Dex += dinv;
            }
        }
        // commit prefetched quarter 0
        { float4* b0 = (float4*)buf[0]; b0[tid] = p0; b0[256+tid] = p1; b0[512+tid] = p2; b0[768+tid] = p3; }
        __syncthreads();

        // layer-2 GEMM: 4 pipelined quarters
        float4 acc = ((const float4*)(bg + HD))[lane];
        int pp = 0;
#pragma unroll
        for (int s = 0; s < 4; s++) {
            float4 q0, q1, q2, q3;
            if (s < 3) {
                const float4* nw = W14 + (s + 1) * 1024;
                q0 = nw[tid]; q1 = nw[256+tid]; q2 = nw[512+tid]; q3 = nw[768+tid];
            }
            const float4* Ws4 = (const float4*)buf[pp];
#pragma unroll
            for (int k = 0; k < 32; k++) {
                float g = gs[warp][s * 32 + k];
                float4 w = Ws4[k * 32 + lane];
                acc.x = fmaf(g, w.x, acc.x); acc.y = fmaf(g, w.y, acc.y);
                acc.z = fmaf(g, w.z, acc.z); acc.w = fmaf(g, w.w, acc.w);
            }
            if (s < 3) {
                __syncthreads();
                float4* nb = (float4*)buf[pp ^ 1];
                nb[tid] = q0; nb[256+tid] = q1; nb[512+tid] = q2; nb[768+tid] = q3;
                __syncthreads();
                pp ^= 1;
            }
        }
        acc.x = fmaxf(acc.x, 0.f); acc.y = fmaxf(acc.y, 0.f);
        acc.z = fmaxf(acc.z, 0.f); acc.w = fmaxf(acc.w, 0.f);
        int base = bk * 8;
        ((float4*)&g_h[base + warp][0])[lane] = acc;
        float dj = rsqrtf((float)(base + warp + 1));
        ((float4*)&hs[warp][0])[lane] = make_float4(acc.x*dj, acc.y*dj, acc.z*dj, acc.w*dj);
        __syncthreads();
        if (tid < HD) {
            float s = 0.f;
#pragma unroll
            for (int w = 0; w < 8; w++) s += hs[w][tid];
            g_P[bk][tid] = s;
        }
    } else {
        // node-constant chain for batch b = bk-31
        int b = bk - 31;
        if (tid < 64) zs[tid] = z[b * 64 + tid];
        __syncthreads();
        {
            int k0 = hf * 32;
            float a0 = 0.f, a1 = 0.f;
#pragma unroll
            for (int k = 0; k < 32; k += 2) {
                a0 = fmaf(zs[k0 + k],     We[(k0 + k) * HD + d],     a0);
                a1 = fmaf(zs[k0 + k + 1], We[(k0 + k + 1) * HD + d], a1);
            }
            red[hf][d] = a0 + a1;
        }
        __syncthreads();
        if (hf == 0) vv[d] = red[0][d] + red[1][d] + be[d];
        __syncthreads();
        for (int l = 0; l < 3; l++) {
            const float* W = Wg + l * HD * HD;
            int k0 = hf * 64;
            float a0 = 0.f, a1 = 0.f;
#pragma unroll
            for (int k = 0; k < 64; k += 2) {
                a0 = fmaf(vv[k0 + k],     W[(k0 + k) * HD + d],     a0);
                a1 = fmaf(vv[k0 + k + 1], W[(k0 + k + 1) * HD + d], a1);
            }
            red[hf][d] = a0 + a1;
            __syncthreads();
            if (hf == 0) vv[d] = fmaxf(red[0][d] + red[1][d] + bg[l * HD + d], 0.f);
            __syncthreads();
        }
        {
            int k0 = hf * 64;
            float a0 = 0.f, b0 = 0.f;
#pragma unroll
            for (int k = 0; k < 64; k++) {
                float vk = vv[k0 + k];
                a0 = fmaf(vk, W1a[(k0 + k) * HD + d], a0);
                b0 = fmaf(vk, W1b[(k0 + k) * HD + d], b0);
            }
            red[hf][d] = a0 + b0;
        }
        __syncthreads();
        float t = 0.f;
        if (hf == 0) t = fmaxf(red[0][d] + red[1][d] + b1[d], 0.f) * W2[d];
        for (int off = 16; off > 0; off >>= 1)
            t += __shfl_down_sync(0xffffffffu, t, off);
        if ((tid & 31) == 0) wsum[tid >> 5] = t;
        __syncthreads();
        if (tid == 0) {
            float s = wsum[0] + wsum[1] + wsum[2] + wsum[3] + b2[0];
            g_pb[b] = 1.f / (1.f + expf(-s));
        }
    }
}

// ---------------------------------------------------------------------------
// K2: block-prefix scan from g_P/g_h -> layer-3 GEMM+ReLU -> A0/B0 GEMMs.
// One continuous 12-quarter double-buffered pipeline across Wg2, W1a, W1b.
// grid 32 x 256
// ---------------------------------------------------------------------------
__global__ void k2(const float* __restrict__ Wg2, const float* __restrict__ bg2,
                   const float* __restrict__ W1a, const float* __restrict__ W1b,
                   const float* __restrict__ b1) {
    __shared__ __align__(16) float buf[2][4096];
    __shared__ __align__(16) float gs[8][HD];
    __shared__ __align__(16) float hs[8][HD];
    int tid = threadIdx.x, warp = tid >> 5, lane = tid & 31;
    int bk = blockIdx.x, base = bk * 8;
    const float4* W0 = (const float4*)Wg2;
    const float4* WA = (const float4*)W1a;
    const float4* WB = (const float4*)W1b;

    // prefetch quarter 0 of Wg2 (hidden behind scan prologue)
    float4 p0 = W0[tid], p1 = W0[256+tid], p2 = W0[512+tid], p3 = W0[768+tid];

    // scan prologue: exclusive prefix from partials, build gs rows
    if (tid < HD) {
        float c = 0.f;
        for (int p = 0; p < bk; p++) c += g_P[p][tid];
#pragma unroll
        for (int j = 0; j < 8; j++) {
            int n = base + j;
            float dinv = rsqrtf((float)(n + 1));
            float h = g_h[n][tid];
            gs[j][tid] = fmaf(dinv, c, dinv * dinv * h);
            c = fmaf(dinv, h, c);
        }
    }
    { float4* b0 = (float4*)buf[0]; b0[tid] = p0; b0[256+tid] = p1; b0[512+tid] = p2; b0[768+tid] = p3; }
    __syncthreads();
    int pp = 0;

    // group 0: Wg2 @ gs -> acc (h3); cross-prefetch WA q0 at s==3
    float4 acc = ((const float4*)bg2)[lane];
#pragma unroll
    for (int s = 0; s < 4; s++) {
        const float4* nw = (s < 3) ? (W0 + (s + 1) * 1024) : WA;
        float4 q0 = nw[tid], q1 = nw[256+tid], q2 = nw[512+tid], q3 = nw[768+tid];
        const float4* Ws4 = (const float4*)buf[pp];
#pragma unroll
        for (int k = 0; k < 32; k++) {
            float g = gs[warp][s * 32 + k];
            float4 w = Ws4[k * 32 + lane];
            acc.x = fmaf(g, w.x, acc.x); acc.y = fmaf(g, w.y, acc.y);
            acc.z = fmaf(g, w.z, acc.z); acc.w = fmaf(g, w.w, acc.w);
        }
        if (s == 3) {
            acc.x = fmaxf(acc.x, 0.f); acc.y = fmaxf(acc.y, 0.f);
            acc.z = fmaxf(acc.z, 0.f); acc.w = fmaxf(acc.w, 0.f);
            ((float4*)&hs[warp][0])[lane] = acc;  // h3 rows (covered by sync below)
        }
        __syncthreads();
        float4* nb = (float4*)buf[pp ^ 1];
        nb[tid] = q0; nb[256+tid] = q1; nb[512+tid] = q2; nb[768+tid] = q3;
        __syncthreads();
        pp ^= 1;
    }

    // group 1: W1a @ hs -> aA; cross-prefetch WB q0 at s==3
    float4 aA = ((const float4*)b1)[lane];
#pragma unroll
    for (int s = 0; s < 4; s++) {
        const float4* nw = (s < 3) ? (WA + (s + 1) * 1024) : WB;
        float4 q0 = nw[tid], q1 = nw[256+tid], q2 = nw[512+tid], q3 = nw[768+tid];
        const float4* Ws4 = (const float4*)buf[pp];
#pragma unroll
        for (int k = 0; k < 32; k++) {
            float h = hs[warp][s * 32 + k];
            float4 w = Ws4[k * 32 + lane];
            aA.x = fmaf(h, w.x, aA.x); aA.y = fmaf(h, w.y, aA.y);
            aA.z = fmaf(h, w.z, aA.z); aA.w = fmaf(h, w.w, aA.w);
        }
        __syncthreads();
        float4* nb = (float4*)buf[pp ^ 1];
        nb[tid] = q0; nb[256+tid] = q1; nb[512+tid] = q2; nb[768+tid] = q3;
        __syncthreads();
        pp ^= 1;
    }
    ((float4*)&g_A0[base + warp][0])[lane] = aA;

    // group 2: W1b @ hs -> aB
    float4 aB = make_float4(0.f, 0.f, 0.f, 0.f);
#pragma unroll
    for (int s = 0; s < 4; s++) {
        float4 q0, q1, q2, q3;
        if (s < 3) {
            const float4* nw = WB + (s + 1) * 1024;
            q0 = nw[tid]; q1 = nw[256+tid]; q2 = nw[512+tid]; q3 = nw[768+tid];
        }
        const float4* Ws4 = (const float4*)buf[pp];
#pragma unroll
        for (int k = 0; k < 32; k++) {
            float h = hs[warp][s * 32 + k];
            float4 w = Ws4[k * 32 + lane];
            aB.x = fmaf(h, w.x, aB.x); aB.y = fmaf(h, w.y, aB.y);
            aB.z = fmaf(h, w.z, aB.z); aB.w = fmaf(h, w.w, aB.w);
        }
        if (s < 3) {
            __syncthreads();
            float4* nb = (float4*)buf[pp ^ 1];
            nb[tid] = q0; nb[256+tid] = q1; nb[512+tid] = q2; nb[768+tid] = q3;
            __syncthreads();
            pp ^= 1;
        }
    }
    ((float4*)&g_B0[base + warp][0])[lane] = aB;
}

// ---------------------------------------------------------------------------
// K3: blocks 0..135 : batch-0 pairwise tiles (16x16, upper triangle, mirrored)
//     blocks 136..195: constant fill for b>=1 (64-row quarters, diag 0)
// grid 196 x 256
// ---------------------------------------------------------------------------
__global__ void k3(const float* __restrict__ W2, const float* __restrict__ b2,
                   float* __restrict__ out) {
    int tid = threadIdx.x;
    int blk = blockIdx.x;
    if (blk < 136) {
        int ti = 0, rem = blk;
        while (rem >= 16 - ti) { rem -= 16 - ti; ti++; }
        int tj = ti + rem;

        __shared__ __align__(16) float a_sh[16][132];
        __shared__ __align__(16) float b_sh[16][132];
        __shared__ __align__(16) float w2s[HD];
        __shared__ float b2s;
        __shared__ float tile[16][17];
        for (int i = tid; i < 512; i += 256) {
            int r = i >> 5, d4 = i & 31;
            ((float4*)&a_sh[r][0])[d4] = ((const float4*)&g_A0[ti * 16 + r][0])[d4];
            ((float4*)&b_sh[r][0])[d4] = ((const float4*)&g_B0[tj * 16 + r][0])[d4];
        }
        if (tid < HD) w2s[tid] = W2[tid];
        if (tid == 0) b2s = b2[0];
        __syncthreads();

        int il = tid >> 4, jl = tid & 15;
        const float4* a4 = (const float4*)&a_sh[il][0];
        const float4* b4 = (const float4*)&b_sh[jl][0];
        const float4* w4 = (const float4*)w2s;
        float ac0 = 0.f, ac1 = 0.f, ac2 = 0.f, ac3 = 0.f;
#pragma unroll
        for (int q = 0; q < 8; q++) {
            { float4 a=a4[q],    b=b4[q],    w=w4[q];
              ac0 = fmaf(fmaxf(a.x+b.x,0.f),w.x,ac0); ac0 = fmaf(fmaxf(a.y+b.y,0.f),w.y,ac0);
              ac0 = fmaf(fmaxf(a.z+b.z,0.f),w.z,ac0); ac0 = fmaf(fmaxf(a.w+b.w,0.f),w.w,ac0); }
            { float4 a=a4[q+8],  b=b4[q+8],  w=w4[q+8];
              ac1 = fmaf(fmaxf(a.x+b.x,0.f),w.x,ac1); ac1 = fmaf(fmaxf(a.y+b.y,0.f),w.y,ac1);
              ac1 = fmaf(fmaxf(a.z+b.z,0.f),w.z,ac1); ac1 = fmaf(fmaxf(a.w+b.w,0.f),w.w,ac1); }
            { float4 a=a4[q+16], b=b4[q+16], w=w4[q+16];
              ac2 = fmaf(fmaxf(a.x+b.x,0.f),w.x,ac2); ac2 = fmaf(fmaxf(a.y+b.y,0.f),w.y,ac2);
              ac2 = fmaf(fmaxf(a.z+b.z,0.f),w.z,ac2); ac2 = fmaf(fmaxf(a.w+b.w,0.f),w.w,ac2); }
            { float4 a=a4[q+24], b=b4[q+24], w=w4[q+24];
              ac3 = fmaf(fmaxf(a.x+b.x,0.f),w.x,ac3); ac3 = fmaf(fmaxf(a.y+b.y,0.f),w.y,ac3);
              ac3 = fmaf(fmaxf(a.z+b.z,0.f),w.z,ac3); ac3 = fmaf(fmaxf(a.w+b.w,0.f),w.w,ac3); }
        }
        float accv = (ac0 + ac1) + (ac2 + ac3);
        tile[il][jl] = 1.f / (1.f + expf(-(accv + b2s)));
        __syncthreads();

        int r = tid >> 4, c = tid & 15;
        if (ti == tj) {
            float vo = (r < c) ? tile[r][c] : ((r > c) ? tile[c][r] : 0.f);
            out[((size_t)(ti * 16 + r)) * NN + ti * 16 + c] = vo;
        } else {
            out[((size_t)(ti * 16 + r)) * NN + tj * 16 + c] = tile[r][c];
            out[((size_t)(tj * 16 + r)) * NN + ti * 16 + c] = tile[c][r];
        }
    } else {
        int fid = blk - 136;          // 0..59
        int b = (fid >> 2) + 1;       // 1..15
        int qr = (fid & 3) * 64;      // quarter row offset
        float p = g_pb[b];
        float4* obase = (float4*)(out + ((size_t)b * NN + qr) * NN);
#pragma unroll
        for (int t = 0; t < 16; t++) {
            int idx = t * 256 + tid;
            int r = idx >> 6, c4 = idx & 63;
            int i = qr + r, j0 = c4 * 4;
            float4 vo;
            vo.x = (i == j0 + 0) ? 0.f : p;
            vo.y = (i == j0 + 1) ? 0.f : p;
            vo.z = (i == j0 + 2) ? 0.f : p;
            vo.w = (i == j0 + 3) ? 0.f : p;
            obase[r * 64 + c4] = vo;
        }
    }
}

// ---------------------------------------------------------------------------
extern "C" void kernel_launch(void* const* d_in, const int* in_sizes, int n_in,
                              void* d_out, int out_size) {
    const float* z   = (const float*)d_in[0];
    const float* We  = (const float*)d_in[1];
    const float* be  = (const float*)d_in[2];
    const float* Wg  = (const float*)d_in[3];
    const float* bg  = (const float*)d_in[4];
    const float* W1a = (const float*)d_in[5];
    const float* W1b = (const float*)d_in[6];
    const float* b1  = (const float*)d_in[7];
    const float* W2  = (const float*)d_in[8];
    const float* b2  = (const float*)d_in[9];
    float* out = (float*)d_out;

    k1<<<47, 256>>>(z, We, be, Wg, bg, W1a, W1b, b1, W2, b2);
    k2<<<32, 256>>>(Wg + 2 * HD * HD, bg + 2 * HD, W1a, W1b, b1);
    k3<<<196, 256>>>(W2, b2, out);
}